// round 17
// baseline (speedup 1.0000x reference)
#include <cuda_runtime.h>
#include <cuda_fp16.h>
#include <cstdint>

#define BB 4
#define SS 2048
#define HH 2048
#define NHH 16
#define HDD 128
#define MROWS (BB*SS)      /* 8192 */
#define QKVN (3*HH)        /* 6144 */

// ---------------- scratch (static device allocations are allowed) ----------
__device__ __half g_xn [(size_t)MROWS * HH];
__device__ __half g_qkv[(size_t)MROWS * QKVN];
__device__ __half g_o  [(size_t)MROWS * HH];
__device__ __half g_wa [(size_t)HH * QKVN];   // c_attn_w fp16, K-major [2048][6144]
__device__ __half g_wp [(size_t)HH * HH];     // c_proj_w fp16, K-major [2048][2048]

__device__ __forceinline__ uint32_t smem_u32(const void* p) {
    uint32_t a;
    asm("{ .reg .u64 t; cvta.to.shared.u64 t, %1; cvt.u32.u64 %0, t; }"
        : "=r"(a) : "l"(p));
    return a;
}

// ---------------- LayerNorm (float4 loads, writes fp16) ---------------------
__global__ void __launch_bounds__(256) ln_kernel(
    const float* __restrict__ x, const float* __restrict__ w,
    const float* __restrict__ b, __half* __restrict__ out)
{
    int row = blockIdx.x;
    const float4* xr = (const float4*)(x + (size_t)row * HH);
    float4 v[2];
    float s = 0.f, s2 = 0.f;
    #pragma unroll
    for (int i = 0; i < 2; i++) {
        v[i] = xr[threadIdx.x + i * 256];
        s  += v[i].x + v[i].y + v[i].z + v[i].w;
        s2 += v[i].x*v[i].x + v[i].y*v[i].y + v[i].z*v[i].z + v[i].w*v[i].w;
    }
    __shared__ float red0[8], red1[8];
    #pragma unroll
    for (int off = 16; off; off >>= 1) {
        s  += __shfl_xor_sync(0xffffffffu, s,  off);
        s2 += __shfl_xor_sync(0xffffffffu, s2, off);
    }
    int warp = threadIdx.x >> 5, lane = threadIdx.x & 31;
    if (lane == 0) { red0[warp] = s; red1[warp] = s2; }
    __syncthreads();
    if (warp == 0) {
        s  = red0[lane & 7];
        s2 = red1[lane & 7];
        #pragma unroll
        for (int off = 4; off; off >>= 1) {
            s  += __shfl_xor_sync(0xffffffffu, s,  off);
            s2 += __shfl_xor_sync(0xffffffffu, s2, off);
        }
        if (lane == 0) { red0[0] = s; red1[0] = s2; }
    }
    __syncthreads();
    float mu  = red0[0] * (1.f / HH);
    float var = red1[0] * (1.f / HH) - mu * mu;
    float rs  = rsqrtf(var + 1e-5f);
    size_t base = (size_t)row * HH;
    #pragma unroll
    for (int i = 0; i < 2; i++) {
        int c = (threadIdx.x + i * 256) * 4;
        float4 wv = *(const float4*)(w + c);
        float4 bv = *(const float4*)(b + c);
        __half2 h0 = __floats2half2_rn((v[i].x - mu) * rs * wv.x + bv.x,
                                       (v[i].y - mu) * rs * wv.y + bv.y);
        __half2 h1 = __floats2half2_rn((v[i].z - mu) * rs * wv.z + bv.z,
                                       (v[i].w - mu) * rs * wv.w + bv.w);
        *(__half2*)(out + base + c)     = h0;
        *(__half2*)(out + base + c + 2) = h1;
    }
}

// ---------------- streaming fp32 -> fp16 cast (coalesced) --------------------
__global__ void __launch_bounds__(256) cast_h_kernel(
    const float* __restrict__ in, __half* __restrict__ out)
{
    size_t i = ((size_t)blockIdx.x * 256 + threadIdx.x) * 4;
    float4 v = *(const float4*)(in + i);
    *(__half2*)(out + i)     = __floats2half2_rn(v.x, v.y);
    *(__half2*)(out + i + 2) = __floats2half2_rn(v.z, v.w);
}

// ---------------- fp16 GEMM: C[M,N] = A[M,K] @ W[K,N] + bias [+res] ---------
// Block tile 128(M) x 128(N), 128 threads (4 warps of 64x64), k-stage 32,
// 4-stage cp.async (wait_group 2 -> 2 stages always in flight), 2 CTAs/SM.
// A frags via ldmatrix.x4 (80B stride); B direct from K-major W via
// ldmatrix.x4.trans (272B stride, conflict-free).
#define GA2_ST 10240                      /* 128 rows * 80B (40 halfs) */
#define GB2_ST 8704                       /* 32 k-rows * 272B (136 halfs) */
#define GB2_BASE (4 * GA2_ST)             /* 40960 */
#define GEMM_SMEM (GB2_BASE + 4 * GB2_ST) /* 75776 */
#define BSTRB 272                         /* B smem row stride in bytes */

template<bool RES, bool HOUT>
__global__ void __launch_bounds__(128, 2) gemm_f16(
    const __half* __restrict__ A, const __half* __restrict__ W,
    const float* __restrict__ bias, const float* __restrict__ res,
    void* __restrict__ Cv, int M, int N, int K)
{
    extern __shared__ char smem[];
    uint32_t sb = smem_u32(smem);

    int tid  = threadIdx.x;
    int warp = tid >> 5, lane = tid & 31;
    int g = lane >> 2, t = lane & 3;
    int wm = (warp & 1) * 64;
    int wn = (warp >> 1) * 64;
    int bm = blockIdx.y * 128;
    int bn = blockIdx.x * 128;

    float acc[4][8][4];
    #pragma unroll
    for (int mi = 0; mi < 4; mi++)
        #pragma unroll
        for (int ni = 0; ni < 8; ni++)
            #pragma unroll
            for (int c = 0; c < 4; c++) acc[mi][ni][c] = 0.f;

    const int KT = K >> 5;          // 64 stages of k=32

    auto fill = [&](int kt) {
        int kk = kt * 32;
        int s = kt & 3;
        #pragma unroll
        for (int p = 0; p < 4; p++) {              // A: 512 x 16B chunks
            int idx = tid + p * 128;
            int r = idx >> 2, c = idx & 3;
            uint32_t d = sb + s * GA2_ST + r * 80 + c * 16;
            const __half* src = A + (size_t)(bm + r) * K + kk + c * 8;
            asm volatile("cp.async.cg.shared.global [%0], [%1], 16;" :: "r"(d), "l"(src) : "memory");
        }
        #pragma unroll
        for (int p = 0; p < 4; p++) {              // B: 32 k-rows x 16 chunks
            int idx = tid + p * 128;
            int r = idx >> 4, c = idx & 15;        // r = k row, c = 16B chunk
            uint32_t d = sb + GB2_BASE + s * GB2_ST + r * BSTRB + c * 16;
            const __half* src = W + (size_t)(kk + r) * N + bn + c * 8;
            asm volatile("cp.async.cg.shared.global [%0], [%1], 16;" :: "r"(d), "l"(src) : "memory");
        }
        asm volatile("cp.async.commit_group;" ::: "memory");
    };

    fill(0);
    fill(1);
    fill(2);

    // ldmatrix lane-address components (constant across stages)
    uint32_t a_lane = (uint32_t)((lane & 15) * 80 + (lane >> 4) * 16);
    uint32_t b_lane = (uint32_t)(((lane & 7) + ((lane >> 3) & 1) * 8) * BSTRB +
                                 (lane >> 4) * 16);

    for (int kt = 0; kt < KT; kt++) {
        asm volatile("cp.async.wait_group 2;" ::: "memory");
        __syncthreads();                           // stage kt ready
        if (kt + 3 < KT) fill(kt + 3);

        int s = kt & 3;
        uint32_t Ab = sb + s * GA2_ST;
        uint32_t Bb = sb + GB2_BASE + s * GB2_ST + b_lane;

        #pragma unroll
        for (int ks = 0; ks < 2; ks++) {           // two k16 steps per stage
            uint32_t af[4][4], bf[8][2];
            uint32_t abase = Ab + a_lane + ks * 32 + (uint32_t)(wm * 80);
            #pragma unroll
            for (int mi = 0; mi < 4; mi++) {
                uint32_t addr = abase + mi * (16 * 80);
                asm volatile(
                    "ldmatrix.sync.aligned.m8n8.x4.shared.b16 {%0,%1,%2,%3}, [%4];"
                    : "=r"(af[mi][0]), "=r"(af[mi][1]), "=r"(af[mi][2]), "=r"(af[mi][3])
                    : "r"(addr));
            }
            uint32_t bbase = Bb + ks * (16 * BSTRB) + (uint32_t)(wn * 2);
            #pragma unroll
            for (int nb = 0; nb < 4; nb++) {       // 4 n16 blocks
                uint32_t addr = bbase + nb * 32;   // +16 cols = 32 bytes
                asm volatile(
                    "ldmatrix.sync.aligned.m8n8.x4.trans.shared.b16 {%0,%1,%2,%3}, [%4];"
                    : "=r"(bf[2*nb][0]), "=r"(bf[2*nb][1]),
                      "=r"(bf[2*nb+1][0]), "=r"(bf[2*nb+1][1])
                    : "r"(addr));
            }
            #pragma unroll
            for (int mi = 0; mi < 4; mi++)
                #pragma unroll
                for (int ni = 0; ni < 8; ni++)
                    asm volatile(
                        "mma.sync.aligned.m16n8k16.row.col.f32.f16.f16.f32 "
                        "{%0,%1,%2,%3},{%4,%5,%6,%7},{%8,%9},{%0,%1,%2,%3};"
                        : "+f"(acc[mi][ni][0]), "+f"(acc[mi][ni][1]),
                          "+f"(acc[mi][ni][2]), "+f"(acc[mi][ni][3])
                        : "r"(af[mi][0]), "r"(af[mi][1]), "r"(af[mi][2]), "r"(af[mi][3]),
                          "r"(bf[ni][0]), "r"(bf[ni][1]));
        }
    }

    // ---- epilogue
    #pragma unroll
    for (int mi = 0; mi < 4; mi++) {
        int r0 = bm + wm + mi * 16 + g;
        #pragma unroll
        for (int ni = 0; ni < 8; ni++) {
            int c0 = bn + wn + ni * 8 + 2 * t;
            #pragma unroll
            for (int half_ = 0; half_ < 2; half_++) {
                int row = r0 + half_ * 8;
                float vx = acc[mi][ni][half_ * 2 + 0] + bias[c0];
                float vy = acc[mi][ni][half_ * 2 + 1] + bias[c0 + 1];
                if (RES) {
                    float2 rr = *(const float2*)(res + (size_t)row * N + c0);
                    vx += rr.x; vy += rr.y;
                }
                if (HOUT) {
                    *(__half2*)((__half*)Cv + (size_t)row * N + c0) =
                        __floats2half2_rn(vx, vy);
                } else {
                    float2 v; v.x = vx; v.y = vy;
                    *(float2*)((float*)Cv + (size_t)row * N + c0) = v;
                }
            }
        }
    }
}

// ---------------- fp16 tensor-core flash attention --------------------------
#define BLKQ 128
#define BLKK 64
#define FH 136                              /* smem row stride in halfs */
#define QB_H  (BLKQ * FH)                   /* 17408 halfs = 34816 B */
#define KVB_H (BLKK * FH)                   /* 8704 halfs = 17408 B */
#define FLASH_SMEM ((QB_H + 4 * KVB_H) * 2) /* 104448 B */

__global__ void __launch_bounds__(256) flash_f16_kernel(
    const __half* __restrict__ qkv, __half* __restrict__ o)
{
    extern __shared__ __half smh[];
    __half* Qs = smh;                        // [128][FH]
    __half* KV = smh + QB_H;                 // 2 x (K[64][FH], V[64][FH])

    int tid  = threadIdx.x;
    int warp = tid >> 5, lane = tid & 31;
    int g = lane >> 2, t = lane & 3;
    int qt = 15 - (int)blockIdx.x;           // heavy tiles first
    int bh = blockIdx.y;
    int b = bh >> 4, h = bh & 15;
    int q0 = qt * BLKQ;
    size_t rowbase = (size_t)b * SS;
    size_t hoff = (size_t)h * 128;
    const float scale = 0.08838834764831845f;   // 1/sqrt(128)

    // ---- load Q tile (fp16, 2048 x 16B chunks)
    #pragma unroll
    for (int i = 0; i < 8; i++) {
        int idx = tid + i * 256;
        int r = idx >> 4, c8 = (idx & 15) * 8;
        uint32_t d = smem_u32(Qs + r * FH + c8);
        const __half* src = qkv + (rowbase + q0 + r) * QKVN + hoff + c8;
        asm volatile("cp.async.cg.shared.global [%0], [%1], 16;" :: "r"(d), "l"(src) : "memory");
    }
    asm volatile("cp.async.commit_group;" ::: "memory");

    auto issue_tile = [&](int kt) {
        int kb = kt * BLKK;
        __half* Kb = KV + (kt & 1) * 2 * KVB_H;
        __half* Vb = Kb + KVB_H;
        #pragma unroll
        for (int i = 0; i < 4; i++) {
            int idx = tid + i * 256;         // 1024 x 16B chunks per operand
            int r = idx >> 4, c8 = (idx & 15) * 8;
            const __half* gk = qkv + (rowbase + kb + r) * QKVN + hoff + 2048 + c8;
            const __half* gv = gk + 2048;
            uint32_t sk = smem_u32(Kb + r * FH + c8);
            uint32_t sv = smem_u32(Vb + r * FH + c8);
            asm volatile("cp.async.cg.shared.global [%0], [%1], 16;" :: "r"(sk), "l"(gk) : "memory");
            asm volatile("cp.async.cg.shared.global [%0], [%1], 16;" :: "r"(sv), "l"(gv) : "memory");
        }
        asm volatile("cp.async.commit_group;" ::: "memory");
    };

    float m0 = -1e30f, m1 = -1e30f, l0 = 0.f, l1 = 0.f;
    float oa[16][4];
    #pragma unroll
    for (int nt = 0; nt < 16; nt++)
        #pragma unroll
        for (int c = 0; c < 4; c++) oa[nt][c] = 0.f;

    const int NKT = (q0 + BLKQ) / BLKK;      // 2*qt + 2
    const int myrow0 = q0 + warp * 16;
    // ldmatrix lane addresses (stride 272B rows -> conflict-free phases)
    uint32_t q_lm = smem_u32(Qs) +
        (uint32_t)((warp * 16 + (lane & 15)) * FH) * 2 + (uint32_t)((lane >> 4) * 16);
    uint32_t k_lane = (uint32_t)(((lane & 7) + ((lane >> 4) << 3)) * FH) * 2 +
                      (uint32_t)(((lane >> 3) & 1) * 16);
    // PV x4.trans lane address (same mapping validated in the GEMM B path)
    uint32_t v_lane = (uint32_t)(((lane & 7) + ((lane >> 3) & 1) * 8) * FH) * 2 +
                      (uint32_t)((lane >> 4) * 16);

    issue_tile(0);

    for (int kt = 0; kt < NKT; kt++) {
        int kb = kt * BLKK;
        asm volatile("cp.async.wait_group 0;" ::: "memory");
        __syncthreads();
        if (kt + 1 < NKT) issue_tile(kt + 1);

        bool active = (kb <= myrow0 + 15);   // warp-uniform
        __half* Kb = KV + (kt & 1) * 2 * KVB_H;
        __half* Vb = Kb + KVB_H;

        if (active) {
            uint32_t kbase = smem_u32(Kb) + k_lane;
            uint32_t vbase = smem_u32(Vb) + v_lane;

            // ---- S = Q @ K^T   (64 k16 mmas/warp, ldmatrix-fed)
            float s[8][4];
            #pragma unroll
            for (int n = 0; n < 8; n++)
                #pragma unroll
                for (int c = 0; c < 4; c++) s[n][c] = 0.f;

            #pragma unroll
            for (int j = 0; j < 8; j++) {            // d chunks of 16
                uint32_t a0, a1, a2, a3;
                asm volatile(
                    "ldmatrix.sync.aligned.m8n8.x4.shared.b16 {%0,%1,%2,%3}, [%4];"
                    : "=r"(a0), "=r"(a1), "=r"(a2), "=r"(a3)
                    : "r"(q_lm + j * 32));
                uint32_t bf[8][2];
                #pragma unroll
                for (int np = 0; np < 4; np++) {
                    uint32_t addr = kbase + np * (16 * FH * 2) + j * 32;
                    asm volatile(
                        "ldmatrix.sync.aligned.m8n8.x4.shared.b16 {%0,%1,%2,%3}, [%4];"
                        : "=r"(bf[2*np][0]), "=r"(bf[2*np][1]),
                          "=r"(bf[2*np+1][0]), "=r"(bf[2*np+1][1])
                        : "r"(addr));
                }
                #pragma unroll
                for (int n = 0; n < 8; n++)
                    asm volatile(
                        "mma.sync.aligned.m16n8k16.row.col.f32.f16.f16.f32 "
                        "{%0,%1,%2,%3},{%4,%5,%6,%7},{%8,%9},{%0,%1,%2,%3};"
                        : "+f"(s[n][0]), "+f"(s[n][1]), "+f"(s[n][2]), "+f"(s[n][3])
                        : "r"(a0), "r"(a1), "r"(a2), "r"(a3),
                          "r"(bf[n][0]), "r"(bf[n][1]));
            }

            // ---- scale, then causal mask
            #pragma unroll
            for (int n = 0; n < 8; n++) {
                s[n][0] *= scale; s[n][1] *= scale;
                s[n][2] *= scale; s[n][3] *= scale;
            }
            if (kb + BLKK - 1 > myrow0) {
                int r0 = myrow0 + g, r1 = r0 + 8;
                #pragma unroll
                for (int n = 0; n < 8; n++) {
                    int c = kb + n * 8 + 2 * t;
                    if (c     > r0) s[n][0] = -1e30f;
                    if (c + 1 > r0) s[n][1] = -1e30f;
                    if (c     > r1) s[n][2] = -1e30f;
                    if (c + 1 > r1) s[n][3] = -1e30f;
                }
            }

            // ---- online softmax (rows g and g+8)
            float mx0 = -1e30f, mx1 = -1e30f;
            #pragma unroll
            for (int n = 0; n < 8; n++) {
                mx0 = fmaxf(mx0, fmaxf(s[n][0], s[n][1]));
                mx1 = fmaxf(mx1, fmaxf(s[n][2], s[n][3]));
            }
            mx0 = fmaxf(mx0, __shfl_xor_sync(0xffffffffu, mx0, 1));
            mx0 = fmaxf(mx0, __shfl_xor_sync(0xffffffffu, mx0, 2));
            mx1 = fmaxf(mx1, __shfl_xor_sync(0xffffffffu, mx1, 1));
            mx1 = fmaxf(mx1, __shfl_xor_sync(0xffffffffu, mx1, 2));
            float mn0 = fmaxf(m0, mx0), mn1 = fmaxf(m1, mx1);
            float al0 = __expf(m0 - mn0), al1 = __expf(m1 - mn1);
            float ls0 = 0.f, ls1 = 0.f;
            #pragma unroll
            for (int n = 0; n < 8; n++) {
                s[n][0] = __expf(s[n][0] - mn0);
                s[n][1] = __expf(s[n][1] - mn0);
                s[n][2] = __expf(s[n][2] - mn1);
                s[n][3] = __expf(s[n][3] - mn1);
                ls0 += s[n][0] + s[n][1];
                ls1 += s[n][2] + s[n][3];
            }
            ls0 += __shfl_xor_sync(0xffffffffu, ls0, 1);
            ls0 += __shfl_xor_sync(0xffffffffu, ls0, 2);
            ls1 += __shfl_xor_sync(0xffffffffu, ls1, 1);
            ls1 += __shfl_xor_sync(0xffffffffu, ls1, 2);
            l0 = l0 * al0 + ls0;  l1 = l1 * al1 + ls1;
            m0 = mn0;  m1 = mn1;
            #pragma unroll
            for (int nt = 0; nt < 16; nt++) {
                oa[nt][0] *= al0; oa[nt][1] *= al0;
                oa[nt][2] *= al1; oa[nt][3] *= al1;
            }

            // ---- O += P @ V   (P pack in regs; V via ldmatrix.x4.trans)
            #pragma unroll
            for (int j = 0; j < 4; j++) {            // seq chunks of 16
                __half2 pa0 = __floats2half2_rn(s[2*j    ][0], s[2*j    ][1]);
                __half2 pa1 = __floats2half2_rn(s[2*j    ][2], s[2*j    ][3]);
                __half2 pa2 = __floats2half2_rn(s[2*j + 1][0], s[2*j + 1][1]);
                __half2 pa3 = __floats2half2_rn(s[2*j + 1][2], s[2*j + 1][3]);
                uint32_t a0 = *(uint32_t*)&pa0;
                uint32_t a1 = *(uint32_t*)&pa1;
                uint32_t a2 = *(uint32_t*)&pa2;
                uint32_t a3 = *(uint32_t*)&pa3;
                uint32_t vrow = vbase + (uint32_t)(16 * j * FH) * 2;
                #pragma unroll
                for (int np = 0; np < 8; np++) {     // 2 n-columns per x4.trans
                    uint32_t b00, b01, b10, b11;
                    uint32_t addr = vrow + np * 32;  // +16 cols = 32 bytes
                    asm volatile(
                        "ldmatrix.sync.aligned.m8n8.x4.trans.shared.b16 {%0,%1,%2,%3}, [%4];"
                        : "=r"(b00), "=r"(b01), "=r"(b10), "=r"(b11) : "r"(addr));
                    asm volatile(
                        "mma.sync.aligned.m16n8k16.row.col.f32.f16.f16.f32 "
                        "{%0,%1,%2,%3},{%4,%5,%6,%7},{%8,%9},{%0,%1,%2,%3};"
                        : "+f"(oa[2*np][0]), "+f"(oa[2*np][1]),
                          "+f"(oa[2*np][2]), "+f"(oa[2*np][3])
                        : "r"(a0), "r"(a1), "r"(a2), "r"(a3), "r"(b00), "r"(b01));
                    asm volatile(
                        "mma.sync.aligned.m16n8k16.row.col.f32.f16.f16.f32 "
                        "{%0,%1,%2,%3},{%4,%5,%6,%7},{%8,%9},{%0,%1,%2,%3};"
                        : "+f"(oa[2*np+1][0]), "+f"(oa[2*np+1][1]),
                          "+f"(oa[2*np+1][2]), "+f"(oa[2*np+1][3])
                        : "r"(a0), "r"(a1), "r"(a2), "r"(a3), "r"(b10), "r"(b11));
                }
            }
        }
    }

    // ---- epilogue: normalize and store fp16 O
    float inv0 = 1.0f / l0, inv1 = 1.0f / l1;
    int r0 = q0 + warp * 16 + g;
    size_t ob0 = (rowbase + r0) * HH + hoff;
    size_t ob1 = ob0 + (size_t)8 * HH;
    #pragma unroll
    for (int nt = 0; nt < 16; nt++) {
        int col = nt * 8 + 2 * t;
        *(__half2*)(o + ob0 + col) = __floats2half2_rn(oa[nt][0] * inv0, oa[nt][1] * inv0);
        *(__half2*)(o + ob1 + col) = __floats2half2_rn(oa[nt][2] * inv1, oa[nt][3] * inv1);
    }
}

// ---------------- launch ----------------------------------------------------
extern "C" void kernel_launch(void* const* d_in, const int* in_sizes, int n_in,
                              void* d_out, int out_size)
{
    const float* x        = (const float*)d_in[0];
    const float* ln_w     = (const float*)d_in[1];
    const float* ln_b     = (const float*)d_in[2];
    const float* c_attn_w = (const float*)d_in[3];
    const float* c_attn_b = (const float*)d_in[4];
    const float* c_proj_w = (const float*)d_in[5];
    const float* c_proj_b = (const float*)d_in[6];
    float* out = (float*)d_out;

    void *p_xn, *p_qkv, *p_o, *p_wa, *p_wp;
    cudaGetSymbolAddress(&p_xn,  g_xn);
    cudaGetSymbolAddress(&p_qkv, g_qkv);
    cudaGetSymbolAddress(&p_o,   g_o);
    cudaGetSymbolAddress(&p_wa,  g_wa);
    cudaGetSymbolAddress(&p_wp,  g_wp);
    __half* xn  = (__half*)p_xn;
    __half* qkv = (__half*)p_qkv;
    __half* ov  = (__half*)p_o;
    __half* wa  = (__half*)p_wa;
    __half* wp  = (__half*)p_wp;

    cudaFuncSetAttribute((const void*)gemm_f16<false, true>,
                         cudaFuncAttributeMaxDynamicSharedMemorySize, GEMM_SMEM);
    cudaFuncSetAttribute((const void*)gemm_f16<true, false>,
                         cudaFuncAttributeMaxDynamicSharedMemorySize, GEMM_SMEM);
    cudaFuncSetAttribute((const void*)flash_f16_kernel,
                         cudaFuncAttributeMaxDynamicSharedMemorySize, FLASH_SMEM);

    // 0. cast weights to fp16 (K-major; no transpose needed)
    cast_h_kernel<<<(HH * QKVN) / 1024, 256>>>(c_attn_w, wa);
    cast_h_kernel<<<(HH * HH) / 1024, 256>>>(c_proj_w, wp);

    // 1. LayerNorm (fp16 out)
    ln_kernel<<<MROWS, 256>>>(x, ln_w, ln_b, xn);

    // 2. QKV projection: [8192,2048] @ [2048,6144] + bias  -> fp16 qkv
    gemm_f16<false, true><<<dim3(QKVN / 128, MROWS / 128), 128, GEMM_SMEM>>>(
        xn, wa, c_attn_b, nullptr, qkv, MROWS, QKVN, HH);

    // 3. causal flash attention (fp16 tensor cores) -> fp16 O
    flash_f16_kernel<<<dim3(SS / BLKQ, BB * NHH), 256, FLASH_SMEM>>>(qkv, ov);

    // 4. output projection + bias + residual -> fp32 out
    gemm_f16<true, false><<<dim3(HH / 128, MROWS / 128), 128, GEMM_SMEM>>>(
        ov, wp, c_proj_b, x, out, MROWS, HH, HH);
}